// round 13
// baseline (speedup 1.0000x reference)
#include <cuda_runtime.h>
#include <cuda_bf16.h>

#define BATCH 512
#define NIN   64
#define ADIM  64

typedef unsigned long long ull;

// ---------------- device scratch (static, no allocation) -------------------
__device__ float4 g_W4[63 * 2 * 1024];   // W_i^c fp32 row-major [i][c][a][k]
__device__ float4 g_P4[31 * 4 * 1024];   // pair products, row-major fp32 [mat][a*16+q]
__device__ uint4  g_Q4[248 * 512];       // quads(240)+triples(8), bf16, chunk layout:
                                         //   mat*512 + q*64 + row ; uint4 = row's k=8q..8q+7

#define AST4 17                          // A row stride in float4 units (68 floats)

// ---- packed f32x2 helpers (sm_103a) ---------------------------------------
__device__ __forceinline__ void ffma2(ull& d, ull a, ull b) {
    asm("fma.rn.f32x2 %0, %1, %2, %0;" : "+l"(d) : "l"(a), "l"(b));
}
__device__ __forceinline__ ull pk2(float x, float y) {
    ull r; asm("mov.b64 %0, {%1, %2};" : "=l"(r) : "f"(x), "f"(y)); return r;
}
__device__ __forceinline__ void up2(ull v, float& x, float& y) {
    asm("mov.b64 {%0, %1}, %2;" : "=f"(x), "=f"(y) : "l"(v));
}
__device__ __forceinline__ float tanh_ap(float x) {
    float r; asm("tanh.approx.f32 %0, %1;" : "=f"(r) : "f"(x)); return r;
}
__device__ __forceinline__ unsigned pkbf2(float x, float y) {
    __nv_bfloat162 p = __floats2bfloat162_rn(x, y);
    return *reinterpret_cast<unsigned*>(&p);
}

// 64x64x64 GEMM consumer: A in padded-f4 smem (stride AST4), B row-major f4.
// thread = (a = tid&63, seg = tid>>6); computes C[a][seg*8 .. +7].
__device__ __forceinline__ void gemm_inner(const float4* sA4, const float4* sB4,
                                           int a, int seg, float* out8) {
    ull c0 = 0, c1 = 0, c2 = 0, c3 = 0;
    const float4* ap = sA4 + a * AST4;
    const ull*    bp = reinterpret_cast<const ull*>(sB4 + seg * 2);
    #pragma unroll
    for (int j4 = 0; j4 < 16; ++j4) {
        float4 av = ap[j4];
        #pragma unroll
        for (int jj = 0; jj < 4; ++jj) {
            float s = (jj == 0) ? av.x : (jj == 1) ? av.y : (jj == 2) ? av.z : av.w;
            ull ss = pk2(s, s);
            const ull* br = bp + (j4 * 4 + jj) * 32;   // 16 f4 per row = 32 u64
            ffma2(c0, ss, br[0]);
            ffma2(c1, ss, br[1]);
            ffma2(c2, ss, br[2]);
            ffma2(c3, ss, br[3]);
        }
    }
    up2(c0, out8[0], out8[1]);
    up2(c1, out8[2], out8[3]);
    up2(c2, out8[4], out8[5]);
    up2(c3, out8[6], out8[7]);
}

// ---------------------------------------------------------------------------
// Kernel 1: k_sig — every sigmoid exactly once (1 MUFU each via tanh.approx).
// CTA (i, quarter q): rows a in [16q, 16q+16). W^1 = s*expa[k], W^0 = expa[k]-W^1.
// grid = 252, block = 256 (one float4 of theta per thread).
// ---------------------------------------------------------------------------
__global__ void __launch_bounds__(256) k_sig(const float* __restrict__ theta,
                                             const float* __restrict__ u) {
    __shared__ float expa[64];
    int blk = blockIdx.x, tid = threadIdx.x;
    int i = blk >> 2, q = blk & 3;

    if (tid < 32) {                              // softmax(u[i])
        float u0 = u[i * 64 + tid], u1 = u[i * 64 + 32 + tid];
        float mm = fmaxf(u0, u1);
        #pragma unroll
        for (int o = 16; o; o >>= 1) mm = fmaxf(mm, __shfl_xor_sync(0xffffffffu, mm, o));
        float ss = __expf(u0 - mm) + __expf(u1 - mm);
        #pragma unroll
        for (int o = 16; o; o >>= 1) ss += __shfl_xor_sync(0xffffffffu, ss, o);
        float lse = mm + __logf(ss);
        expa[tid]      = __expf(u0 - lse);
        expa[tid + 32] = __expf(u1 - lse);
    }
    __syncthreads();

    int idx4 = q * 256 + tid;                    // float4 index within matrix i
    int k0 = (idx4 * 4) & 63;
    float4 t4 = reinterpret_cast<const float4*>(theta)[i * 1024 + idx4];
    float s0 = fmaf(0.5f, tanh_ap(0.5f * t4.x), 0.5f);
    float s1 = fmaf(0.5f, tanh_ap(0.5f * t4.y), 0.5f);
    float s2 = fmaf(0.5f, tanh_ap(0.5f * t4.z), 0.5f);
    float s3 = fmaf(0.5f, tanh_ap(0.5f * t4.w), 0.5f);
    float e0 = expa[k0], e1 = expa[k0 + 1], e2 = expa[k0 + 2], e3 = expa[k0 + 3];
    float4 w1 = make_float4(s0 * e0, s1 * e1, s2 * e2, s3 * e3);
    float4 w0 = make_float4(e0 - w1.x, e1 - w1.y, e2 - w1.z, e3 - w1.w);
    g_W4[(i * 2 + 1) * 1024 + idx4] = w1;
    g_W4[(i * 2 + 0) * 1024 + idx4] = w0;
}

// ---------------------------------------------------------------------------
// Kernel 2: pairs P = W_{2t}^{c0} @ W_{2t+1}^{c1} — pure loads + GEMM (no MUFU).
// grid = 124, block = 512.
// ---------------------------------------------------------------------------
__global__ void __launch_bounds__(512) k_pair() {
    __shared__ __align__(16) float sA[64 * AST4 * 4];
    __shared__ __align__(16) float sB[4096];

    int blk = blockIdx.x, tid = threadIdx.x;
    int t = blk >> 2, vv = blk & 3;
    const float4* A4 = g_W4 + ((2 * t)     * 2 + (vv >> 1)) * 1024;
    const float4* B4 = g_W4 + ((2 * t + 1) * 2 + (vv & 1))  * 1024;

    float4* sA4 = reinterpret_cast<float4*>(sA);
    float4* sB4 = reinterpret_cast<float4*>(sB);
    #pragma unroll
    for (int r = 0; r < 2; ++r) {
        int idx4 = tid + 512 * r;                // = row*16 + q
        int row = idx4 >> 4, q = idx4 & 15;
        sA4[row * AST4 + q] = A4[idx4];
        sB4[idx4] = B4[idx4];
    }
    __syncthreads();

    int a = tid & 63, seg = tid >> 6;
    float acc[8];
    gemm_inner(sA4, sB4, a, seg, acc);

    float4* C4 = g_P4 + blk * 1024;
    C4[a * 16 + seg * 2]     = make_float4(acc[0], acc[1], acc[2], acc[3]);
    C4[a * 16 + seg * 2 + 1] = make_float4(acc[4], acc[5], acc[6], acc[7]);
}

// ---------------------------------------------------------------------------
// Kernel 3: quads Q = P_{2t}^{v>>2} @ P_{2t+1}^{v&3} (blk<240);
//           triples T = P_30^{v>>1} @ W62^{v&1} (blk 240..247, W62 from g_W4).
// Output bf16 chunk layout for k_main. grid = 248, block = 512.
// ---------------------------------------------------------------------------
__global__ void __launch_bounds__(512) k_quad() {
    __shared__ __align__(16) float sA[64 * AST4 * 4];
    __shared__ __align__(16) float sB[4096];
    int blk = blockIdx.x, tid = threadIdx.x;

    float4* sA4 = reinterpret_cast<float4*>(sA);
    float4* sB4 = reinterpret_cast<float4*>(sB);

    const float4 *A4, *B4;
    if (blk < 240) {
        int t = blk >> 4, v = blk & 15;
        A4 = g_P4 + ((2 * t)     * 4 + (v >> 2)) * 1024;
        B4 = g_P4 + ((2 * t + 1) * 4 + (v & 3))  * 1024;
    } else {
        int v = blk - 240;
        A4 = g_P4 + (30 * 4 + (v >> 1)) * 1024;
        B4 = g_W4 + (62 * 2 + (v & 1)) * 1024;
    }
    #pragma unroll
    for (int r = 0; r < 2; ++r) {
        int idx4 = tid + 512 * r;                // = row*16 + q
        int row = idx4 >> 4, q = idx4 & 15;
        sA4[row * AST4 + q] = A4[idx4];
        sB4[idx4] = B4[idx4];
    }
    __syncthreads();

    int a = tid & 63, seg = tid >> 6;
    float acc[8];
    gemm_inner(sA4, sB4, a, seg, acc);

    uint4 uo;
    uo.x = pkbf2(acc[0], acc[1]);
    uo.y = pkbf2(acc[2], acc[3]);
    uo.z = pkbf2(acc[4], acc[5]);
    uo.w = pkbf2(acc[6], acc[7]);
    g_Q4[blk * 512 + seg * 64 + a] = uo;
}

// ---------------------------------------------------------------------------
// Kernel 4: per-batch stabilized log-semiring chain, 16 steps, bf16 weights,
// single __syncthreads per step (warp-local exp scaling on even steps).
// Step 0 = triple m0; even sp>0 -> t = 15-2sp; odd sp -> t = 14-2sp.
// grid = 512, block = 64.  (Validated in R10/R11.)
// ---------------------------------------------------------------------------
__device__ __forceinline__ int matq(unsigned long long bits, int t) {
    unsigned nib = (unsigned)(bits >> (4 * t)) & 0xFu;
    unsigned v = ((nib & 1u) << 3) | ((nib & 2u) << 1) | ((nib & 4u) >> 1) | ((nib & 8u) >> 3);
    return t * 16 + (int)v;
}

__device__ __forceinline__ void dotb(const uint4* wr, const float4* e4,
                                     float& lo, float& hi) {
    float a0 = 0.f, a1 = 0.f, a2 = 0.f, a3 = 0.f;
    float b0 = 0.f, b1 = 0.f, b2 = 0.f, b3 = 0.f;
    #pragma unroll
    for (int q = 0; q < 4; ++q) {
        float4 e0 = e4[2 * q], e1 = e4[2 * q + 1];
        uint4 uw = wr[q];
        a0 = fmaf(__uint_as_float(uw.x << 16),          e0.x, a0);
        a1 = fmaf(__uint_as_float(uw.x & 0xffff0000u),  e0.y, a1);
        a2 = fmaf(__uint_as_float(uw.y << 16),          e0.z, a2);
        a3 = fmaf(__uint_as_float(uw.y & 0xffff0000u),  e0.w, a3);
        a0 = fmaf(__uint_as_float(uw.z << 16),          e1.x, a0);
        a1 = fmaf(__uint_as_float(uw.z & 0xffff0000u),  e1.y, a1);
        a2 = fmaf(__uint_as_float(uw.w << 16),          e1.z, a2);
        a3 = fmaf(__uint_as_float(uw.w & 0xffff0000u),  e1.w, a3);
    }
    #pragma unroll
    for (int q = 4; q < 8; ++q) {
        float4 e0 = e4[2 * q], e1 = e4[2 * q + 1];
        uint4 uw = wr[q];
        b0 = fmaf(__uint_as_float(uw.x << 16),          e0.x, b0);
        b1 = fmaf(__uint_as_float(uw.x & 0xffff0000u),  e0.y, b1);
        b2 = fmaf(__uint_as_float(uw.y << 16),          e0.z, b2);
        b3 = fmaf(__uint_as_float(uw.y & 0xffff0000u),  e0.w, b3);
        b0 = fmaf(__uint_as_float(uw.z << 16),          e1.x, b0);
        b1 = fmaf(__uint_as_float(uw.z & 0xffff0000u),  e1.y, b1);
        b2 = fmaf(__uint_as_float(uw.w << 16),          e1.z, b2);
        b3 = fmaf(__uint_as_float(uw.w & 0xffff0000u),  e1.w, b3);
    }
    lo = (a0 + a1) + (a2 + a3);
    hi = (b0 + b1) + (b2 + b3);
}

__global__ void __launch_bounds__(64) k_main(const float* __restrict__ x,
                                             const float* __restrict__ theta,
                                             float* __restrict__ out) {
    int tid = threadIdx.x, w = tid >> 5, l = tid & 31;
    int b = blockIdx.x;

    __shared__ __align__(16) float se[2][64];
    __shared__ float red[2];
    __shared__ unsigned sbits[2];

    float xa = x[b * 64 + tid];
    unsigned bal = __ballot_sync(0xffffffffu, xa != 0.0f);
    if (l == 0) sbits[w] = bal;
    __syncthreads();
    unsigned long long bits =
        ((unsigned long long)sbits[1] << 32) | (unsigned long long)sbits[0];

    // v init: log p(x63 | a, col 0)
    int c63 = (int)(bits >> 63) & 1;
    float t63 = theta[63 * 4096 + tid * 64];
    float v = (c63 ? t63 : 0.0f) - fmaxf(t63, 0.0f)
            - __logf(1.0f + __expf(-fabsf(t63)));

    int m0 = 240 + (((int)(bits >> 60) & 1) << 2)
                 + (((int)(bits >> 61) & 1) << 1)
                 +  ((int)(bits >> 62) & 1);

    float m = 0.0f;
    uint4 wr[8];

    #pragma unroll 1
    for (int sp = 0; sp < 8; ++sp) {
        // ---- even step: refresh max (warp-local scaling), 1 sync ----
        {
            int mat = (sp == 0) ? m0 : matq(bits, 15 - 2 * sp);   // t=13,11,...,1
            const uint4* base = g_Q4 + mat * 512;
            #pragma unroll
            for (int q = 0; q < 8; ++q) wr[q] = base[q * 64 + tid];  // issue early

            float wm = v;
            #pragma unroll
            for (int o = 16; o; o >>= 1) wm = fmaxf(wm, __shfl_xor_sync(0xffffffffu, wm, o));
            if (l == 0) red[w] = wm;
            se[0][tid] = __expf(v - wm);          // warp-local scale
            __syncthreads();
            m = fmaxf(red[0], red[1]);
            float s0 = __expf(red[0] - m);
            float s1 = __expf(red[1] - m);
            float lo, hi;
            dotb(wr, reinterpret_cast<const float4*>(se[0]), lo, hi);
            v = __logf(fmaf(s0, lo, s1 * hi)) + m;
        }
        // ---- odd step: stale max, 1 sync ----
        {
            int mat = matq(bits, 14 - 2 * sp);    // t=14,12,...,0
            const uint4* base = g_Q4 + mat * 512;
            #pragma unroll
            for (int q = 0; q < 8; ++q) wr[q] = base[q * 64 + tid];

            se[1][tid] = __expf(v - m);
            __syncthreads();
            float lo, hi;
            dotb(wr, reinterpret_cast<const float4*>(se[1]), lo, hi);
            v = __logf(lo + hi) + m;
        }
    }

    out[b * 64 + tid] = v;
}

// ---------------------------------------------------------------------------
extern "C" void kernel_launch(void* const* d_in, const int* in_sizes, int n_in,
                              void* d_out, int out_size) {
    const float* x     = nullptr;
    const float* theta = nullptr;
    const float* u     = nullptr;
    for (int i = 0; i < n_in; ++i) {
        if      (in_sizes[i] == BATCH * NIN)       x     = (const float*)d_in[i];
        else if (in_sizes[i] == NIN * ADIM * ADIM) theta = (const float*)d_in[i];
        else if (in_sizes[i] == (NIN - 1) * ADIM)  u     = (const float*)d_in[i];
    }

    k_sig <<<252, 256>>>(theta, u);
    k_pair<<<124, 512>>>();
    k_quad<<<248, 512>>>();
    k_main<<<BATCH, 64>>>(x, theta, (float*)d_out);
}

// round 14
// speedup vs baseline: 1.0012x; 1.0012x over previous
#include <cuda_runtime.h>
#include <cuda_bf16.h>

#define BATCH 512
#define NIN   64
#define ADIM  64

typedef unsigned long long ull;

// ---------------- device scratch (static, no allocation) -------------------
__device__ float4 g_W4[63 * 2 * 1024];   // W_i^c fp32 row-major [i][c][a][k]
__device__ float4 g_P4[31 * 4 * 1024];   // pair products, row-major fp32 [mat][a*16+q]
__device__ uint4  g_Q4[248 * 512];       // quads(240)+triples(8), bf16, chunk layout:
                                         //   mat*512 + q*64 + row ; uint4 = row's k=8q..8q+7

#define AST4 17                          // A row stride in float4 units (68 floats)

// ---- packed f32x2 helpers (sm_103a) ---------------------------------------
__device__ __forceinline__ void ffma2(ull& d, ull a, ull b) {
    asm("fma.rn.f32x2 %0, %1, %2, %0;" : "+l"(d) : "l"(a), "l"(b));
}
__device__ __forceinline__ ull pk2(float x, float y) {
    ull r; asm("mov.b64 %0, {%1, %2};" : "=l"(r) : "f"(x), "f"(y)); return r;
}
__device__ __forceinline__ void up2(ull v, float& x, float& y) {
    asm("mov.b64 {%0, %1}, %2;" : "=f"(x), "=f"(y) : "l"(v));
}
__device__ __forceinline__ float tanh_ap(float x) {
    float r; asm("tanh.approx.f32 %0, %1;" : "=f"(r) : "f"(x)); return r;
}
__device__ __forceinline__ unsigned pkbf2(float x, float y) {
    __nv_bfloat162 p = __floats2bfloat162_rn(x, y);
    return *reinterpret_cast<unsigned*>(&p);
}

// Half-GEMM: thread (a, seg 0..3) computes C[a][h*32 + seg*8 .. +7].
// A padded f4 smem (stride AST4), B half-tile row-major 8 f4 per row.
__device__ __forceinline__ void gemm_half(const float4* sA4, const float4* sB4,
                                          int a, int seg, float* out8) {
    ull c0 = 0, c1 = 0, c2 = 0, c3 = 0;
    const float4* ap = sA4 + a * AST4;
    const ull*    bp = reinterpret_cast<const ull*>(sB4 + seg * 2);
    #pragma unroll
    for (int j4 = 0; j4 < 16; ++j4) {
        float4 av = ap[j4];
        #pragma unroll
        for (int jj = 0; jj < 4; ++jj) {
            float s = (jj == 0) ? av.x : (jj == 1) ? av.y : (jj == 2) ? av.z : av.w;
            ull ss = pk2(s, s);
            const ull* br = bp + (j4 * 4 + jj) * 16;   // row stride = 8 f4 = 16 u64
            ffma2(c0, ss, br[0]);
            ffma2(c1, ss, br[1]);
            ffma2(c2, ss, br[2]);
            ffma2(c3, ss, br[3]);
        }
    }
    up2(c0, out8[0], out8[1]);
    up2(c1, out8[2], out8[3]);
    up2(c2, out8[4], out8[5]);
    up2(c3, out8[6], out8[7]);
}

// ---------------------------------------------------------------------------
// Kernel 1: k_sig — every sigmoid exactly once (1 MUFU via tanh.approx).
// CTA (i, quarter q). W^1 = s*expa[k], W^0 = expa[k]-W^1. grid=252, block=256.
// ---------------------------------------------------------------------------
__global__ void __launch_bounds__(256) k_sig(const float* __restrict__ theta,
                                             const float* __restrict__ u) {
    __shared__ float expa[64];
    int blk = blockIdx.x, tid = threadIdx.x;
    int i = blk >> 2, q = blk & 3;

    if (tid < 32) {                              // softmax(u[i])
        float u0 = u[i * 64 + tid], u1 = u[i * 64 + 32 + tid];
        float mm = fmaxf(u0, u1);
        #pragma unroll
        for (int o = 16; o; o >>= 1) mm = fmaxf(mm, __shfl_xor_sync(0xffffffffu, mm, o));
        float ss = __expf(u0 - mm) + __expf(u1 - mm);
        #pragma unroll
        for (int o = 16; o; o >>= 1) ss += __shfl_xor_sync(0xffffffffu, ss, o);
        float lse = mm + __logf(ss);
        expa[tid]      = __expf(u0 - lse);
        expa[tid + 32] = __expf(u1 - lse);
    }
    __syncthreads();

    int idx4 = q * 256 + tid;
    int k0 = (idx4 * 4) & 63;
    float4 t4 = reinterpret_cast<const float4*>(theta)[i * 1024 + idx4];
    float s0 = fmaf(0.5f, tanh_ap(0.5f * t4.x), 0.5f);
    float s1 = fmaf(0.5f, tanh_ap(0.5f * t4.y), 0.5f);
    float s2 = fmaf(0.5f, tanh_ap(0.5f * t4.z), 0.5f);
    float s3 = fmaf(0.5f, tanh_ap(0.5f * t4.w), 0.5f);
    float e0 = expa[k0], e1 = expa[k0 + 1], e2 = expa[k0 + 2], e3 = expa[k0 + 3];
    float4 w1 = make_float4(s0 * e0, s1 * e1, s2 * e2, s3 * e3);
    float4 w0 = make_float4(e0 - w1.x, e1 - w1.y, e2 - w1.z, e3 - w1.w);
    g_W4[(i * 2 + 1) * 1024 + idx4] = w1;
    g_W4[(i * 2 + 0) * 1024 + idx4] = w0;
}

// ---------------------------------------------------------------------------
// Kernel 2: pairs P = W_{2t}^{c0} @ W_{2t+1}^{c1}, half-split for load balance.
// blk = pm*2 + h ; CTA computes output columns [32h, 32h+32). grid=248, block=256.
// ---------------------------------------------------------------------------
__global__ void __launch_bounds__(256) k_pair() {
    __shared__ __align__(16) float sA[64 * AST4 * 4];
    __shared__ __align__(16) float sB[2048];

    int blk = blockIdx.x, tid = threadIdx.x;
    int pm = blk >> 1, h = blk & 1;
    int t = pm >> 2, vv = pm & 3;
    const float4* A4 = g_W4 + ((2 * t)     * 2 + (vv >> 1)) * 1024;
    const float4* B4 = g_W4 + ((2 * t + 1) * 2 + (vv & 1))  * 1024;

    float4* sA4 = reinterpret_cast<float4*>(sA);
    float4* sB4 = reinterpret_cast<float4*>(sB);
    #pragma unroll
    for (int r = 0; r < 4; ++r) {
        int idx4 = tid + 256 * r;                // full A: 1024 f4
        int row = idx4 >> 4, q = idx4 & 15;
        sA4[row * AST4 + q] = A4[idx4];
    }
    #pragma unroll
    for (int r = 0; r < 2; ++r) {
        int idx = tid + 256 * r;                 // half B: 512 f4 (8 per row)
        int row = idx >> 3, q = idx & 7;
        sB4[idx] = B4[row * 16 + h * 8 + q];
    }
    __syncthreads();

    int a = tid & 63, seg = tid >> 6;            // seg 0..3
    float acc[8];
    gemm_half(sA4, sB4, a, seg, acc);

    float4* C4 = g_P4 + pm * 1024;
    C4[a * 16 + h * 8 + seg * 2]     = make_float4(acc[0], acc[1], acc[2], acc[3]);
    C4[a * 16 + h * 8 + seg * 2 + 1] = make_float4(acc[4], acc[5], acc[6], acc[7]);
}

// ---------------------------------------------------------------------------
// Kernel 3: quads/triples, half-split. blk = qm*2 + h.
// qm<240: Q = P_{2t}^{v>>2} @ P_{2t+1}^{v&3}; qm 240..247: T = P_30^{v>>1} @ W62^{v&1}.
// Output bf16 chunk layout. grid = 496, block = 256.
// ---------------------------------------------------------------------------
__global__ void __launch_bounds__(256) k_quad() {
    __shared__ __align__(16) float sA[64 * AST4 * 4];
    __shared__ __align__(16) float sB[2048];
    int blk = blockIdx.x, tid = threadIdx.x;
    int qm = blk >> 1, h = blk & 1;

    const float4 *A4, *B4;
    if (qm < 240) {
        int t = qm >> 4, v = qm & 15;
        A4 = g_P4 + ((2 * t)     * 4 + (v >> 2)) * 1024;
        B4 = g_P4 + ((2 * t + 1) * 4 + (v & 3))  * 1024;
    } else {
        int v = qm - 240;
        A4 = g_P4 + (30 * 4 + (v >> 1)) * 1024;
        B4 = g_W4 + (62 * 2 + (v & 1)) * 1024;
    }

    float4* sA4 = reinterpret_cast<float4*>(sA);
    float4* sB4 = reinterpret_cast<float4*>(sB);
    #pragma unroll
    for (int r = 0; r < 4; ++r) {
        int idx4 = tid + 256 * r;
        int row = idx4 >> 4, q = idx4 & 15;
        sA4[row * AST4 + q] = A4[idx4];
    }
    #pragma unroll
    for (int r = 0; r < 2; ++r) {
        int idx = tid + 256 * r;
        int row = idx >> 3, q = idx & 7;
        sB4[idx] = B4[row * 16 + h * 8 + q];
    }
    __syncthreads();

    int a = tid & 63, seg = tid >> 6;
    float acc[8];
    gemm_half(sA4, sB4, a, seg, acc);

    // thread's 8 cols = k in [h*32+seg*8, +8) = chunk (h*4+seg)
    uint4 uo;
    uo.x = pkbf2(acc[0], acc[1]);
    uo.y = pkbf2(acc[2], acc[3]);
    uo.z = pkbf2(acc[4], acc[5]);
    uo.w = pkbf2(acc[6], acc[7]);
    g_Q4[qm * 512 + (h * 4 + seg) * 64 + a] = uo;
}

// ---------------------------------------------------------------------------
// Kernel 4: log-semiring chain, 16 steps, bf16 weights, single sync per step,
// TWO batches per CTA interleaved in registers (ILP latency hiding).
// grid = 256, block = 64.
// ---------------------------------------------------------------------------
__device__ __forceinline__ int matq(unsigned long long bits, int t) {
    unsigned nib = (unsigned)(bits >> (4 * t)) & 0xFu;
    unsigned v = ((nib & 1u) << 3) | ((nib & 2u) << 1) | ((nib & 4u) >> 1) | ((nib & 8u) >> 3);
    return t * 16 + (int)v;
}

__device__ __forceinline__ void dotb(const uint4* wr, const float4* e4,
                                     float& lo, float& hi) {
    float a0 = 0.f, a1 = 0.f, a2 = 0.f, a3 = 0.f;
    float b0 = 0.f, b1 = 0.f, b2 = 0.f, b3 = 0.f;
    #pragma unroll
    for (int q = 0; q < 4; ++q) {
        float4 e0 = e4[2 * q], e1 = e4[2 * q + 1];
        uint4 uw = wr[q];
        a0 = fmaf(__uint_as_float(uw.x << 16),          e0.x, a0);
        a1 = fmaf(__uint_as_float(uw.x & 0xffff0000u),  e0.y, a1);
        a2 = fmaf(__uint_as_float(uw.y << 16),          e0.z, a2);
        a3 = fmaf(__uint_as_float(uw.y & 0xffff0000u),  e0.w, a3);
        a0 = fmaf(__uint_as_float(uw.z << 16),          e1.x, a0);
        a1 = fmaf(__uint_as_float(uw.z & 0xffff0000u),  e1.y, a1);
        a2 = fmaf(__uint_as_float(uw.w << 16),          e1.z, a2);
        a3 = fmaf(__uint_as_float(uw.w & 0xffff0000u),  e1.w, a3);
    }
    #pragma unroll
    for (int q = 4; q < 8; ++q) {
        float4 e0 = e4[2 * q], e1 = e4[2 * q + 1];
        uint4 uw = wr[q];
        b0 = fmaf(__uint_as_float(uw.x << 16),          e0.x, b0);
        b1 = fmaf(__uint_as_float(uw.x & 0xffff0000u),  e0.y, b1);
        b2 = fmaf(__uint_as_float(uw.y << 16),          e0.z, b2);
        b3 = fmaf(__uint_as_float(uw.y & 0xffff0000u),  e0.w, b3);
        b0 = fmaf(__uint_as_float(uw.z << 16),          e1.x, b0);
        b1 = fmaf(__uint_as_float(uw.z & 0xffff0000u),  e1.y, b1);
        b2 = fmaf(__uint_as_float(uw.w << 16),          e1.z, b2);
        b3 = fmaf(__uint_as_float(uw.w & 0xffff0000u),  e1.w, b3);
    }
    lo = (a0 + a1) + (a2 + a3);
    hi = (b0 + b1) + (b2 + b3);
}

__global__ void __launch_bounds__(64) k_main(const float* __restrict__ x,
                                             const float* __restrict__ theta,
                                             float* __restrict__ out) {
    int tid = threadIdx.x, w = tid >> 5, l = tid & 31;
    int b0 = blockIdx.x * 2, b1 = b0 + 1;

    __shared__ __align__(16) float se0[2][64];
    __shared__ __align__(16) float se1[2][64];
    __shared__ float red0[2], red1[2];
    __shared__ unsigned sb[4];

    float xa0 = x[b0 * 64 + tid];
    float xa1 = x[b1 * 64 + tid];
    unsigned bal0 = __ballot_sync(0xffffffffu, xa0 != 0.0f);
    unsigned bal1 = __ballot_sync(0xffffffffu, xa1 != 0.0f);
    if (l == 0) { sb[w] = bal0; sb[2 + w] = bal1; }
    __syncthreads();
    unsigned long long bits0 = ((unsigned long long)sb[1] << 32) | (unsigned long long)sb[0];
    unsigned long long bits1 = ((unsigned long long)sb[3] << 32) | (unsigned long long)sb[2];

    // v init: log p(x63 | a, col 0)  (theta shared by both batches)
    float t63 = theta[63 * 4096 + tid * 64];
    float base_lp = -fmaxf(t63, 0.0f) - __logf(1.0f + __expf(-fabsf(t63)));
    float v0 = (((int)(bits0 >> 63) & 1) ? t63 : 0.0f) + base_lp;
    float v1 = (((int)(bits1 >> 63) & 1) ? t63 : 0.0f) + base_lp;

    int m00 = 240 + (((int)(bits0 >> 60) & 1) << 2)
                  + (((int)(bits0 >> 61) & 1) << 1)
                  +  ((int)(bits0 >> 62) & 1);
    int m01 = 240 + (((int)(bits1 >> 60) & 1) << 2)
                  + (((int)(bits1 >> 61) & 1) << 1)
                  +  ((int)(bits1 >> 62) & 1);

    float m0 = 0.0f, m1 = 0.0f;
    uint4 wr0[8], wr1[8];

    #pragma unroll 1
    for (int sp = 0; sp < 8; ++sp) {
        // ---- even step: refresh max (warp-local scaling), 1 sync ----
        {
            int mat0 = (sp == 0) ? m00 : matq(bits0, 15 - 2 * sp);
            int mat1 = (sp == 0) ? m01 : matq(bits1, 15 - 2 * sp);
            const uint4* ba0 = g_Q4 + mat0 * 512;
            const uint4* ba1 = g_Q4 + mat1 * 512;
            #pragma unroll
            for (int q = 0; q < 8; ++q) { wr0[q] = ba0[q * 64 + tid]; wr1[q] = ba1[q * 64 + tid]; }

            float wm0 = v0, wm1 = v1;
            #pragma unroll
            for (int o = 16; o; o >>= 1) {
                wm0 = fmaxf(wm0, __shfl_xor_sync(0xffffffffu, wm0, o));
                wm1 = fmaxf(wm1, __shfl_xor_sync(0xffffffffu, wm1, o));
            }
            if (l == 0) { red0[w] = wm0; red1[w] = wm1; }
            se0[0][tid] = __expf(v0 - wm0);
            se1[0][tid] = __expf(v1 - wm1);
            __syncthreads();
            m0 = fmaxf(red0[0], red0[1]);
            m1 = fmaxf(red1[0], red1[1]);
            float s00 = __expf(red0[0] - m0), s01 = __expf(red0[1] - m0);
            float s10 = __expf(red1[0] - m1), s11 = __expf(red1[1] - m1);
            float lo0, hi0, lo1, hi1;
            dotb(wr0, reinterpret_cast<const float4*>(se0[0]), lo0, hi0);
            dotb(wr1, reinterpret_cast<const float4*>(se1[0]), lo1, hi1);
            v0 = __logf(fmaf(s00, lo0, s01 * hi0)) + m0;
            v1 = __logf(fmaf(s10, lo1, s11 * hi1)) + m1;
        }
        // ---- odd step: stale max, 1 sync ----
        {
            int mat0 = matq(bits0, 14 - 2 * sp);
            int mat1 = matq(bits1, 14 - 2 * sp);
            const uint4* ba0 = g_Q4 + mat0 * 512;
            const uint4* ba1 = g_Q4 + mat1 * 512;
            #pragma unroll
            for (int q = 0; q < 8; ++q) { wr0[q] = ba0[q * 64 + tid]; wr1[q] = ba1[q * 64 + tid]; }

            se0[1][tid] = __expf(v0 - m0);
            se1[1][tid] = __expf(v1 - m1);
            __syncthreads();
            float lo0, hi0, lo1, hi1;
            dotb(wr0, reinterpret_cast<const float4*>(se0[1]), lo0, hi0);
            dotb(wr1, reinterpret_cast<const float4*>(se1[1]), lo1, hi1);
            v0 = __logf(lo0 + hi0) + m0;
            v1 = __logf(lo1 + hi1) + m1;
        }
    }

    out[b0 * 64 + tid] = v0;
    out[b1 * 64 + tid] = v1;
}

// ---------------------------------------------------------------------------
extern "C" void kernel_launch(void* const* d_in, const int* in_sizes, int n_in,
                              void* d_out, int out_size) {
    const float* x     = nullptr;
    const float* theta = nullptr;
    const float* u     = nullptr;
    for (int i = 0; i < n_in; ++i) {
        if      (in_sizes[i] == BATCH * NIN)       x     = (const float*)d_in[i];
        else if (in_sizes[i] == NIN * ADIM * ADIM) theta = (const float*)d_in[i];
        else if (in_sizes[i] == (NIN - 1) * ADIM)  u     = (const float*)d_in[i];
    }

    k_sig <<<252, 256>>>(theta, u);
    k_pair<<<248, 256>>>();
    k_quad<<<496, 256>>>();
    k_main<<<BATCH / 2, 64>>>(x, theta, (float*)d_out);
}